// round 1
// baseline (speedup 1.0000x reference)
#include <cuda_runtime.h>

#define NN   100000
#define EE   1600000
#define DIN  128
#define DHID 64
#define DOUT 16

// Scratch (allocation-free rule: __device__ globals). ~90 MB total.
__device__ float g_dinv[NN];            // degree accumulator, then d^{-1/2}
__device__ float g_hs1[NN * DHID];      // (x@W1) * dinv[row]
__device__ float g_acc1[NN * DHID];     // scatter accumulator, layer 1
__device__ float g_x1[NN * DHID];       // relu(layer1) output
__device__ float g_hs2[NN * DOUT];      // (x1@W2) * dinv[row]
__device__ float g_acc2[NN * DOUT];     // scatter accumulator, layer 2

// ---------------------------------------------------------------------------
__global__ void k_init() {
    int i = blockIdx.x * blockDim.x + threadIdx.x;
    if (i < NN * DHID) g_acc1[i] = 0.f;
    if (i < NN * DOUT) g_acc2[i] = 0.f;
    if (i < NN)        g_dinv[i] = 1.f;   // self-loop contributes 1 to deg
}

__global__ void k_deg(const int* __restrict__ dst) {
    int e = blockIdx.x * blockDim.x + threadIdx.x;
    if (e < EE) atomicAdd(&g_dinv[dst[e]], 1.f);
}

__global__ void k_rsqrt() {
    int i = blockIdx.x * blockDim.x + threadIdx.x;
    if (i < NN) g_dinv[i] = rsqrtf(g_dinv[i]);
}

// ---------------------------------------------------------------------------
// GEMM1: hs1[row] = (x[row] @ W1) * dinv[row].  W1 (128x64 = 32KB) in smem.
// Block: (8,32) = 256 threads; each thread computes 8 consecutive output cols
// for one row via 2 float4 smem loads per k.
__global__ void k_gemm1(const float* __restrict__ x, const float* __restrict__ W1) {
    __shared__ float4 sW[DIN * DHID / 4];   // 2048 float4 = 32 KB
    int t = threadIdx.y * 8 + threadIdx.x;
    const float4* W4 = (const float4*)W1;
    for (int i = t; i < DIN * DHID / 4; i += 256) sW[i] = W4[i];
    __syncthreads();

    int row = blockIdx.x * 32 + threadIdx.y;
    if (row >= NN) return;
    int tx = threadIdx.x;
    const float* xr = x + (long)row * DIN;

    float acc[8];
    #pragma unroll
    for (int j = 0; j < 8; j++) acc[j] = 0.f;

    #pragma unroll 4
    for (int k = 0; k < DIN; k++) {
        float xv = xr[k];
        float4 w0 = sW[k * 16 + tx * 2];
        float4 w1 = sW[k * 16 + tx * 2 + 1];
        acc[0] += xv * w0.x; acc[1] += xv * w0.y;
        acc[2] += xv * w0.z; acc[3] += xv * w0.w;
        acc[4] += xv * w1.x; acc[5] += xv * w1.y;
        acc[6] += xv * w1.z; acc[7] += xv * w1.w;
    }
    float dv = g_dinv[row];
    float4* o = (float4*)(g_hs1 + (long)row * DHID + tx * 8);
    o[0] = make_float4(acc[0] * dv, acc[1] * dv, acc[2] * dv, acc[3] * dv);
    o[1] = make_float4(acc[4] * dv, acc[5] * dv, acc[6] * dv, acc[7] * dv);
}

// ---------------------------------------------------------------------------
// Scatter layer 1: one warp per edge, each lane handles 2 of the 64 features.
__global__ void k_scatter1(const int* __restrict__ src, const int* __restrict__ dst) {
    int t = blockIdx.x * blockDim.x + threadIdx.x;
    int e = t >> 5, lane = t & 31;
    if (e >= EE) return;
    int s = src[e], d = dst[e];
    float2 v = ((const float2*)g_hs1)[(long)s * 32 + lane];
    float* a = g_acc1 + (long)d * DHID + lane * 2;
    atomicAdd(a,     v.x);
    atomicAdd(a + 1, v.y);
}

// x1 = relu(dinv[n] * (acc1 + hs1_self) + b1)
__global__ void k_fin1(const float* __restrict__ b1) {
    int i = blockIdx.x * blockDim.x + threadIdx.x;
    if (i >= NN * DHID) return;
    int n = i >> 6, c = i & 63;
    float v = g_dinv[n] * (g_acc1[i] + g_hs1[i]) + b1[c];
    g_x1[i] = fmaxf(v, 0.f);
}

// ---------------------------------------------------------------------------
// GEMM2: hs2[row] = (x1[row] @ W2) * dinv[row].  W2 (64x16 = 4KB) in smem.
// Block (16,16): thread = (col, row-in-block).
__global__ void k_gemm2(const float* __restrict__ W2) {
    __shared__ float sW[DHID * DOUT];
    int t = threadIdx.y * 16 + threadIdx.x;
    for (int i = t; i < DHID * DOUT; i += 256) sW[i] = W2[i];
    __syncthreads();

    int row = blockIdx.x * 16 + threadIdx.y;
    if (row >= NN) return;
    int col = threadIdx.x;
    const float* xr = g_x1 + (long)row * DHID;
    float acc = 0.f;
    #pragma unroll 8
    for (int k = 0; k < DHID; k++) acc += xr[k] * sW[k * DOUT + col];
    g_hs2[(long)row * DOUT + col] = acc * g_dinv[row];
}

// Scatter layer 2: 4 threads per edge, each handles a float4 (4 of 16 feats).
__global__ void k_scatter2(const int* __restrict__ src, const int* __restrict__ dst) {
    int t = blockIdx.x * blockDim.x + threadIdx.x;
    int e = t >> 2, q = t & 3;
    if (e >= EE) return;
    int s = src[e], d = dst[e];
    float4 v = ((const float4*)g_hs2)[(long)s * 4 + q];
    float* a = g_acc2 + (long)d * DOUT + q * 4;
    atomicAdd(a,     v.x);
    atomicAdd(a + 1, v.y);
    atomicAdd(a + 2, v.z);
    atomicAdd(a + 3, v.w);
}

// Finalize layer 2 + log_softmax over 16 cols. One thread per node.
__global__ void k_fin2(const float* __restrict__ b2, float* __restrict__ out) {
    int n = blockIdx.x * blockDim.x + threadIdx.x;
    if (n >= NN) return;
    float dv = g_dinv[n];
    float v[DOUT];
    float m = -1e30f;
    #pragma unroll
    for (int c = 0; c < DOUT; c++) {
        float t = dv * (g_acc2[n * DOUT + c] + g_hs2[n * DOUT + c]) + b2[c];
        v[c] = t;
        m = fmaxf(m, t);
    }
    float s = 0.f;
    #pragma unroll
    for (int c = 0; c < DOUT; c++) s += expf(v[c] - m);
    float ls = m + logf(s);
    #pragma unroll
    for (int c = 0; c < DOUT; c++) out[n * DOUT + c] = v[c] - ls;
}

// ---------------------------------------------------------------------------
extern "C" void kernel_launch(void* const* d_in, const int* in_sizes, int n_in,
                              void* d_out, int out_size) {
    const float* x  = (const float*)d_in[0];
    const int*   ei = (const int*)  d_in[1];
    const float* W1 = (const float*)d_in[2];
    const float* b1 = (const float*)d_in[3];
    const float* W2 = (const float*)d_in[4];
    const float* b2 = (const float*)d_in[5];
    const int* src = ei;        // edge_index[0]
    const int* dst = ei + EE;   // edge_index[1]

    k_init  <<<(NN * DHID + 255) / 256, 256>>>();
    k_deg   <<<(EE + 255) / 256, 256>>>(dst);
    k_rsqrt <<<(NN + 255) / 256, 256>>>();
    k_gemm1 <<<(NN + 31) / 32, dim3(8, 32)>>>(x, W1);
    k_scatter1<<<(EE * 32) / 256, 256>>>(src, dst);          // 51.2M threads
    k_fin1  <<<(NN * DHID + 255) / 256, 256>>>(b1);
    k_gemm2 <<<(NN + 15) / 16, dim3(16, 16)>>>(W2);
    k_scatter2<<<(EE * 4 + 255) / 256, 256>>>(src, dst);
    k_fin2  <<<(NN + 255) / 256, 256>>>(b2, (float*)d_out);
}

// round 3
// speedup vs baseline: 2.4649x; 2.4649x over previous
#include <cuda_runtime.h>

#define NN   100000
#define EE   1600000
#define DIN  128
#define DHID 64
#define DOUT 16

// Scratch (allocation-free rule: __device__ globals).
__device__ float g_dinv[NN];
__device__ float g_hs1[NN * DHID];
__device__ float g_acc1[NN * DHID];
__device__ float g_x1[NN * DHID];
__device__ float g_hs2[NN * DOUT];
__device__ float g_acc2[NN * DOUT];

// ---------------------------------------------------------------------------
__global__ void k_init() {
    int i = blockIdx.x * blockDim.x + threadIdx.x;
    float4 z = make_float4(0.f, 0.f, 0.f, 0.f);
    if (i < NN * DHID / 4) ((float4*)g_acc1)[i] = z;
    if (i < NN * DOUT / 4) ((float4*)g_acc2)[i] = z;
    if (i < NN)            g_dinv[i] = 1.f;   // self-loop contributes 1 to deg
}

__global__ void k_deg(const int* __restrict__ dst) {
    int e = blockIdx.x * blockDim.x + threadIdx.x;
    if (e < EE) atomicAdd(&g_dinv[dst[e]], 1.f);
}

__global__ void k_rsqrt() {
    int i = blockIdx.x * blockDim.x + threadIdx.x;
    if (i < NN) g_dinv[i] = rsqrtf(g_dinv[i]);
}

// ---------------------------------------------------------------------------
// GEMM1: hs1[row] = (x[row] @ W1) * dinv[row].
// Block: 256 threads -> 256 rows x 64 cols tile. Thread: 8 rows x 8 cols.
// Dynamic smem: sW[128*64] (32KB) + xs[256][33] (33.8KB) = 66.5KB.
#define KC 32
#define GEMM1_SMEM ((DIN * DHID + 256 * (KC + 1)) * 4)
__global__ __launch_bounds__(256) void k_gemm1(const float* __restrict__ x,
                                               const float* __restrict__ W1) {
    extern __shared__ float smem[];
    float* sW = smem;                          // [k][col], 32 KB
    float (*xs)[KC + 1] = (float (*)[KC + 1])(smem + DIN * DHID);

    int tid = threadIdx.x;
    int tx  = tid & 7;    // col-group (8 cols)
    int ty  = tid >> 3;   // row-group (0..31)
    int rowBase = blockIdx.x * 256;

    {   // load W1 whole
        const float4* W4 = (const float4*)W1;
        float4* sW4 = (float4*)sW;
        #pragma unroll
        for (int i = 0; i < DIN * DHID / 4 / 256; i++)
            sW4[tid + i * 256] = W4[tid + i * 256];
    }

    float acc[8][8];
    #pragma unroll
    for (int r = 0; r < 8; r++)
        #pragma unroll
        for (int c = 0; c < 8; c++) acc[r][c] = 0.f;

    for (int kc = 0; kc < DIN; kc += KC) {
        __syncthreads();
        // stage x[rowBase..rowBase+255][kc..kc+31] into xs
        #pragma unroll
        for (int it = 0; it < 8; it++) {
            int f   = tid + it * 256;        // float4 id in [0,2048)
            int row = f >> 3;
            int k4  = (f & 7) * 4;
            float4 v = make_float4(0.f, 0.f, 0.f, 0.f);
            if (rowBase + row < NN)
                v = ((const float4*)x)[(long)(rowBase + row) * (DIN / 4) + ((kc + k4) >> 2)];
            xs[row][k4 + 0] = v.x;
            xs[row][k4 + 1] = v.y;
            xs[row][k4 + 2] = v.z;
            xs[row][k4 + 3] = v.w;
        }
        __syncthreads();

        #pragma unroll
        for (int k = 0; k < KC; k++) {
            float4 w0 = *(const float4*)&sW[(kc + k) * DHID + tx * 8];
            float4 w1 = *(const float4*)&sW[(kc + k) * DHID + tx * 8 + 4];
            #pragma unroll
            for (int r = 0; r < 8; r++) {
                float xv = xs[ty * 8 + r][k];
                acc[r][0] += xv * w0.x; acc[r][1] += xv * w0.y;
                acc[r][2] += xv * w0.z; acc[r][3] += xv * w0.w;
                acc[r][4] += xv * w1.x; acc[r][5] += xv * w1.y;
                acc[r][6] += xv * w1.z; acc[r][7] += xv * w1.w;
            }
        }
    }

    #pragma unroll
    for (int r = 0; r < 8; r++) {
        int row = rowBase + ty * 8 + r;
        if (row < NN) {
            float dv = g_dinv[row];
            float4* o = (float4*)(g_hs1 + (long)row * DHID + tx * 8);
            o[0] = make_float4(acc[r][0] * dv, acc[r][1] * dv, acc[r][2] * dv, acc[r][3] * dv);
            o[1] = make_float4(acc[r][4] * dv, acc[r][5] * dv, acc[r][6] * dv, acc[r][7] * dv);
        }
    }
}

// ---------------------------------------------------------------------------
__device__ __forceinline__ void red_add_v4(float* a, float4 v) {
    asm volatile("red.global.add.v4.f32 [%0], {%1,%2,%3,%4};"
                 :: "l"(a), "f"(v.x), "f"(v.y), "f"(v.z), "f"(v.w)
                 : "memory");
}

// Scatter layer 1: 16 threads per edge, each handles one float4 of 64 feats.
__global__ void k_scatter1(const int* __restrict__ src, const int* __restrict__ dst) {
    long t = (long)blockIdx.x * blockDim.x + threadIdx.x;
    int e = (int)(t >> 4), q = (int)(t & 15);
    if (e >= EE) return;
    int s = __ldg(src + e), d = __ldg(dst + e);
    float4 v = ((const float4*)g_hs1)[(long)s * 16 + q];
    red_add_v4(g_acc1 + (long)d * DHID + q * 4, v);
}

// x1 = relu(dinv[n] * (acc1 + hs1_self) + b1), vectorized float4
__global__ void k_fin1(const float* __restrict__ b1) {
    int i = blockIdx.x * blockDim.x + threadIdx.x;   // float4 index
    if (i >= NN * DHID / 4) return;
    int n = i >> 4, c4 = i & 15;
    float dv = g_dinv[n];
    float4 a = ((const float4*)g_acc1)[i];
    float4 h = ((const float4*)g_hs1)[i];
    float4 b = ((const float4*)b1)[c4];
    float4 o;
    o.x = fmaxf(dv * (a.x + h.x) + b.x, 0.f);
    o.y = fmaxf(dv * (a.y + h.y) + b.y, 0.f);
    o.z = fmaxf(dv * (a.z + h.z) + b.z, 0.f);
    o.w = fmaxf(dv * (a.w + h.w) + b.w, 0.f);
    ((float4*)g_x1)[i] = o;
}

// ---------------------------------------------------------------------------
// GEMM2: hs2 = (x1 @ W2) * dinv. Block: 128 threads -> 256 rows x 16 cols.
// Thread: 8 rows x 4 cols. Static smem: 4KB + 33.8KB = 37.9KB (under 48KB).
__global__ __launch_bounds__(128) void k_gemm2(const float* __restrict__ W2) {
    __shared__ float sW[DHID * DOUT];     // 4 KB, [k][col]
    __shared__ float xs[256][KC + 1];

    int tid = threadIdx.x;
    int tx  = tid & 3;    // col-group (4 cols)
    int ty  = tid >> 2;   // row-group (0..31)
    int rowBase = blockIdx.x * 256;

    {
        const float4* W4 = (const float4*)W2;
        float4* sW4 = (float4*)sW;
        #pragma unroll
        for (int i = 0; i < DHID * DOUT / 4 / 128; i++)
            sW4[tid + i * 128] = W4[tid + i * 128];
    }

    float acc[8][4];
    #pragma unroll
    for (int r = 0; r < 8; r++)
        #pragma unroll
        for (int c = 0; c < 4; c++) acc[r][c] = 0.f;

    for (int kc = 0; kc < DHID; kc += KC) {
        __syncthreads();
        #pragma unroll
        for (int it = 0; it < 16; it++) {
            int f   = tid + it * 128;
            int row = f >> 3;
            int k4  = (f & 7) * 4;
            float4 v = make_float4(0.f, 0.f, 0.f, 0.f);
            if (rowBase + row < NN)
                v = ((const float4*)g_x1)[(long)(rowBase + row) * (DHID / 4) + ((kc + k4) >> 2)];
            xs[row][k4 + 0] = v.x;
            xs[row][k4 + 1] = v.y;
            xs[row][k4 + 2] = v.z;
            xs[row][k4 + 3] = v.w;
        }
        __syncthreads();

        #pragma unroll
        for (int k = 0; k < KC; k++) {
            float4 w = *(const float4*)&sW[(kc + k) * DOUT + tx * 4];
            #pragma unroll
            for (int r = 0; r < 8; r++) {
                float xv = xs[ty * 8 + r][k];
                acc[r][0] += xv * w.x; acc[r][1] += xv * w.y;
                acc[r][2] += xv * w.z; acc[r][3] += xv * w.w;
            }
        }
    }

    #pragma unroll
    for (int r = 0; r < 8; r++) {
        int row = rowBase + ty * 8 + r;
        if (row < NN) {
            float dv = g_dinv[row];
            ((float4*)(g_hs2 + (long)row * DOUT))[tx] =
                make_float4(acc[r][0] * dv, acc[r][1] * dv, acc[r][2] * dv, acc[r][3] * dv);
        }
    }
}

// Scatter layer 2: 4 threads per edge, each handles a float4 (4 of 16 feats).
__global__ void k_scatter2(const int* __restrict__ src, const int* __restrict__ dst) {
    long t = (long)blockIdx.x * blockDim.x + threadIdx.x;
    int e = (int)(t >> 2), q = (int)(t & 3);
    if (e >= EE) return;
    int s = __ldg(src + e), d = __ldg(dst + e);
    float4 v = ((const float4*)g_hs2)[(long)s * 4 + q];
    red_add_v4(g_acc2 + (long)d * DOUT + q * 4, v);
}

// Finalize layer 2 + log_softmax over 16 cols. One thread per node.
__global__ void k_fin2(const float* __restrict__ b2, float* __restrict__ out) {
    int n = blockIdx.x * blockDim.x + threadIdx.x;
    if (n >= NN) return;
    float dv = g_dinv[n];
    float v[DOUT];
    float m = -1e30f;
    #pragma unroll
    for (int c4 = 0; c4 < 4; c4++) {
        float4 a = ((const float4*)g_acc2)[n * 4 + c4];
        float4 h = ((const float4*)g_hs2)[n * 4 + c4];
        float4 b = ((const float4*)b2)[c4];
        v[c4 * 4 + 0] = dv * (a.x + h.x) + b.x;
        v[c4 * 4 + 1] = dv * (a.y + h.y) + b.y;
        v[c4 * 4 + 2] = dv * (a.z + h.z) + b.z;
        v[c4 * 4 + 3] = dv * (a.w + h.w) + b.w;
    }
    #pragma unroll
    for (int c = 0; c < DOUT; c++) m = fmaxf(m, v[c]);
    float s = 0.f;
    #pragma unroll
    for (int c = 0; c < DOUT; c++) s += expf(v[c] - m);
    float ls = m + logf(s);
    #pragma unroll
    for (int c = 0; c < DOUT; c++) out[n * DOUT + c] = v[c] - ls;
}

// ---------------------------------------------------------------------------
extern "C" void kernel_launch(void* const* d_in, const int* in_sizes, int n_in,
                              void* d_out, int out_size) {
    const float* x  = (const float*)d_in[0];
    const int*   ei = (const int*)  d_in[1];
    const float* W1 = (const float*)d_in[2];
    const float* b1 = (const float*)d_in[3];
    const float* W2 = (const float*)d_in[4];
    const float* b2 = (const float*)d_in[5];
    const int* src = ei;        // edge_index[0]
    const int* dst = ei + EE;   // edge_index[1]

    // Immediate (non-stream) runtime call: capture-safe, no allocation.
    cudaFuncSetAttribute(k_gemm1, cudaFuncAttributeMaxDynamicSharedMemorySize,
                         GEMM1_SMEM);

    k_init    <<<(NN * DHID / 4 + 255) / 256, 256>>>();
    k_deg     <<<(EE + 255) / 256, 256>>>(dst);
    k_rsqrt   <<<(NN + 255) / 256, 256>>>();
    k_gemm1   <<<(NN + 255) / 256, 256, GEMM1_SMEM>>>(x, W1);
    k_scatter1<<<(int)(((long)EE * 16 + 255) / 256), 256>>>(src, dst);
    k_fin1    <<<(NN * DHID / 4 + 255) / 256, 256>>>(b1);
    k_gemm2   <<<(NN + 255) / 256, 128>>>(W2);
    k_scatter2<<<(int)(((long)EE * 4 + 255) / 256), 256>>>(src, dst);
    k_fin2    <<<(NN + 255) / 256, 256>>>(b2, (float*)d_out);
}

// round 5
// speedup vs baseline: 3.1222x; 1.2667x over previous
#include <cuda_runtime.h>

#define NN   100000
#define EE   1600000
#define DIN  128
#define DHID 64
#define DOUT 16
#define NB1  ((NN + 1023) / 1024)   // 98 scan blocks

// Scratch (__device__ globals; allocation-free rule).
__device__ float g_dinv[NN];
__device__ float g_hs1[NN * DHID];
__device__ float g_x1[NN * DHID];
__device__ float g_hs2[NN * DOUT];
__device__ int   g_cnt[NN];        // in-degree (excl self)
__device__ int   g_tmp[NB1 * 1024];// block-inclusive scan
__device__ int   g_bsum[NB1];      // per-block sums
__device__ int   g_offx[NN];       // exclusive CSR offsets
__device__ int   g_cur[NN];        // fill cursors
__device__ int   g_esrc[EE];       // CSR: src per dst-sorted slot

// ---------------------------------------------------------------------------
__global__ void k_zero() {
    int i = blockIdx.x * blockDim.x + threadIdx.x;
    if (i < NN) g_cnt[i] = 0;
}

__global__ void k_count(const int* __restrict__ dst) {
    int e = blockIdx.x * blockDim.x + threadIdx.x;
    if (e < EE) atomicAdd(&g_cnt[dst[e]], 1);
}

// Block-wise inclusive scan of g_cnt (1024/block), partials to g_bsum.
__global__ __launch_bounds__(1024) void k_scan1() {
    __shared__ int ws[32];
    int i = blockIdx.x * 1024 + threadIdx.x;
    int lane = threadIdx.x & 31, wid = threadIdx.x >> 5;
    int v = (i < NN) ? g_cnt[i] : 0;
    int s = v;
    #pragma unroll
    for (int d = 1; d < 32; d <<= 1) {
        int t = __shfl_up_sync(0xffffffff, s, d);
        if (lane >= d) s += t;
    }
    if (lane == 31) ws[wid] = s;
    __syncthreads();
    if (wid == 0) {
        int w = ws[lane];
        #pragma unroll
        for (int d = 1; d < 32; d <<= 1) {
            int t = __shfl_up_sync(0xffffffff, w, d);
            if (lane >= d) w += t;
        }
        ws[lane] = w;
    }
    __syncthreads();
    int incl = s + (wid > 0 ? ws[wid - 1] : 0);
    g_tmp[i] = incl;
    if (threadIdx.x == 1023) g_bsum[blockIdx.x] = incl;
}

// Scan the 98 block sums (single block, 128 threads).
__global__ void k_scan2() {
    __shared__ int ws[4];
    int t = threadIdx.x;
    int lane = t & 31, wid = t >> 5;
    int v = (t < NB1) ? g_bsum[t] : 0;
    int s = v;
    #pragma unroll
    for (int d = 1; d < 32; d <<= 1) {
        int u = __shfl_up_sync(0xffffffff, s, d);
        if (lane >= d) s += u;
    }
    if (lane == 31) ws[wid] = s;
    __syncthreads();
    if (wid == 0 && lane < 4) {
        int w = ws[lane];
        #pragma unroll
        for (int d = 1; d < 4; d <<= 1) {
            int u = __shfl_up_sync(0xf, w, d);
            if (lane >= d) w += u;
        }
        ws[lane] = w;
    }
    __syncthreads();
    int incl = s + (wid > 0 ? ws[wid - 1] : 0);
    if (t < NB1) g_bsum[t] = incl;
}

// Exclusive offsets + cursors + dinv.
__global__ __launch_bounds__(1024) void k_scan3() {
    int i = blockIdx.x * 1024 + threadIdx.x;
    if (i >= NN) return;
    int c = g_cnt[i];
    int excl = g_tmp[i] - c + (blockIdx.x > 0 ? g_bsum[blockIdx.x - 1] : 0);
    g_offx[i] = excl;
    g_cur[i]  = excl;
    g_dinv[i] = rsqrtf((float)(c + 1));   // +1 self-loop
}

__global__ void k_fill(const int* __restrict__ src, const int* __restrict__ dst) {
    int e = blockIdx.x * blockDim.x + threadIdx.x;
    if (e >= EE) return;
    int d = dst[e];
    int p = atomicAdd(&g_cur[d], 1);
    g_esrc[p] = src[e];
}

// ---------------------------------------------------------------------------
// GEMM1: hs1[row] = (x[row] @ W1) * dinv[row]. 256 thr -> 256x64 tile, 8x8/thr.
#define KC 32
#define GEMM1_SMEM ((DIN * DHID + 256 * (KC + 1)) * 4)
__global__ __launch_bounds__(256) void k_gemm1(const float* __restrict__ x,
                                               const float* __restrict__ W1) {
    extern __shared__ float smem[];
    float* sW = smem;
    float (*xs)[KC + 1] = (float (*)[KC + 1])(smem + DIN * DHID);

    int tid = threadIdx.x;
    int tx  = tid & 7;
    int ty  = tid >> 3;
    int rowBase = blockIdx.x * 256;

    {
        const float4* W4 = (const float4*)W1;
        float4* sW4 = (float4*)sW;
        #pragma unroll
        for (int i = 0; i < DIN * DHID / 4 / 256; i++)
            sW4[tid + i * 256] = W4[tid + i * 256];
    }

    float acc[8][8];
    #pragma unroll
    for (int r = 0; r < 8; r++)
        #pragma unroll
        for (int c = 0; c < 8; c++) acc[r][c] = 0.f;

    for (int kc = 0; kc < DIN; kc += KC) {
        __syncthreads();
        #pragma unroll
        for (int it = 0; it < 8; it++) {
            int f   = tid + it * 256;
            int row = f >> 3;
            int k4  = (f & 7) * 4;
            float4 v = make_float4(0.f, 0.f, 0.f, 0.f);
            if (rowBase + row < NN)
                v = ((const float4*)x)[(long)(rowBase + row) * (DIN / 4) + ((kc + k4) >> 2)];
            xs[row][k4 + 0] = v.x;
            xs[row][k4 + 1] = v.y;
            xs[row][k4 + 2] = v.z;
            xs[row][k4 + 3] = v.w;
        }
        __syncthreads();

        #pragma unroll
        for (int k = 0; k < KC; k++) {
            float4 w0 = *(const float4*)&sW[(kc + k) * DHID + tx * 8];
            float4 w1 = *(const float4*)&sW[(kc + k) * DHID + tx * 8 + 4];
            #pragma unroll
            for (int r = 0; r < 8; r++) {
                float xv = xs[ty * 8 + r][k];
                acc[r][0] += xv * w0.x; acc[r][1] += xv * w0.y;
                acc[r][2] += xv * w0.z; acc[r][3] += xv * w0.w;
                acc[r][4] += xv * w1.x; acc[r][5] += xv * w1.y;
                acc[r][6] += xv * w1.z; acc[r][7] += xv * w1.w;
            }
        }
    }

    #pragma unroll
    for (int r = 0; r < 8; r++) {
        int row = rowBase + ty * 8 + r;
        if (row < NN) {
            float dv = g_dinv[row];
            float4* o = (float4*)(g_hs1 + (long)row * DHID + tx * 8);
            o[0] = make_float4(acc[r][0] * dv, acc[r][1] * dv, acc[r][2] * dv, acc[r][3] * dv);
            o[1] = make_float4(acc[r][4] * dv, acc[r][5] * dv, acc[r][6] * dv, acc[r][7] * dv);
        }
    }
}

// ---------------------------------------------------------------------------
// agg1: one warp per node. lane owns feats [2*lane, 2*lane+1].
// Uniform trip count across the warp -> full-mask shuffles are safe here.
__global__ __launch_bounds__(256) void k_agg1(const float* __restrict__ b1) {
    int warp = (blockIdx.x * 256 + threadIdx.x) >> 5;
    int lane = threadIdx.x & 31;
    if (warp >= NN) return;
    int n   = warp;
    int off = g_offx[n];
    int cnt = g_cnt[n];

    const float2* hs = (const float2*)g_hs1;
    float2 acc = hs[(long)n * 32 + lane];      // self-loop term

    for (int base = 0; base < cnt; base += 32) {
        int idx = base + lane;
        int e   = (idx < cnt) ? g_esrc[off + idx] : 0;
        int m   = min(32, cnt - base);
        for (int j = 0; j < m; j++) {
            int s = __shfl_sync(0xffffffff, e, j);
            float2 v = hs[(long)s * 32 + lane];
            acc.x += v.x;
            acc.y += v.y;
        }
    }

    float dv = g_dinv[n];
    float2 b = ((const float2*)b1)[lane];
    float2 o;
    o.x = fmaxf(dv * acc.x + b.x, 0.f);
    o.y = fmaxf(dv * acc.y + b.y, 0.f);
    ((float2*)g_x1)[(long)n * 32 + lane] = o;
}

// ---------------------------------------------------------------------------
// GEMM2: hs2 = (x1 @ W2) * dinv. 128 thr -> 256x16 tile, 8x4/thr.
__global__ __launch_bounds__(128) void k_gemm2(const float* __restrict__ W2) {
    __shared__ float sW[DHID * DOUT];
    __shared__ float xs[256][KC + 1];

    int tid = threadIdx.x;
    int tx  = tid & 3;
    int ty  = tid >> 2;
    int rowBase = blockIdx.x * 256;

    {
        const float4* W4 = (const float4*)W2;
        float4* sW4 = (float4*)sW;
        #pragma unroll
        for (int i = 0; i < DHID * DOUT / 4 / 128; i++)
            sW4[tid + i * 128] = W4[tid + i * 128];
    }

    float acc[8][4];
    #pragma unroll
    for (int r = 0; r < 8; r++)
        #pragma unroll
        for (int c = 0; c < 4; c++) acc[r][c] = 0.f;

    for (int kc = 0; kc < DHID; kc += KC) {
        __syncthreads();
        #pragma unroll
        for (int it = 0; it < 16; it++) {
            int f   = tid + it * 128;
            int row = f >> 3;
            int k4  = (f & 7) * 4;
            float4 v = make_float4(0.f, 0.f, 0.f, 0.f);
            if (rowBase + row < NN)
                v = ((const float4*)g_x1)[(long)(rowBase + row) * (DHID / 4) + ((kc + k4) >> 2)];
            xs[row][k4 + 0] = v.x;
            xs[row][k4 + 1] = v.y;
            xs[row][k4 + 2] = v.z;
            xs[row][k4 + 3] = v.w;
        }
        __syncthreads();

        #pragma unroll
        for (int k = 0; k < KC; k++) {
            float4 w = *(const float4*)&sW[(kc + k) * DOUT + tx * 4];
            #pragma unroll
            for (int r = 0; r < 8; r++) {
                float xv = xs[ty * 8 + r][k];
                acc[r][0] += xv * w.x; acc[r][1] += xv * w.y;
                acc[r][2] += xv * w.z; acc[r][3] += xv * w.w;
            }
        }
    }

    #pragma unroll
    for (int r = 0; r < 8; r++) {
        int row = rowBase + ty * 8 + r;
        if (row < NN) {
            float dv = g_dinv[row];
            ((float4*)(g_hs2 + (long)row * DOUT))[tx] =
                make_float4(acc[r][0] * dv, acc[r][1] * dv, acc[r][2] * dv, acc[r][3] * dv);
        }
    }
}

// ---------------------------------------------------------------------------
// agg2: 8-lane group per node (4 nodes/warp), lane owns 2 of 16 feats.
// Groups in a warp have DIFFERENT trip counts -> all shuffles use the
// per-group mask (0xFF << (lane & 24)); full-mask here traps.
__global__ __launch_bounds__(256) void k_agg2(const float* __restrict__ b2,
                                              float* __restrict__ out) {
    int grp  = (blockIdx.x * 256 + threadIdx.x) >> 3;   // node id
    int gl   = threadIdx.x & 7;                         // lane in group
    unsigned gmask = 0xFFu << (threadIdx.x & 24);       // this group's lanes
    if (grp >= NN) return;
    int n   = grp;
    int off = g_offx[n];
    int cnt = g_cnt[n];

    const float2* hs = (const float2*)g_hs2;
    float2 acc = hs[(long)n * 8 + gl];                  // self-loop

    for (int base = 0; base < cnt; base += 8) {
        int idx = base + gl;
        int e   = (idx < cnt) ? g_esrc[off + idx] : 0;
        int m   = min(8, cnt - base);
        for (int j = 0; j < m; j++) {
            int s = __shfl_sync(gmask, e, j, 8);
            float2 v = hs[(long)s * 8 + gl];
            acc.x += v.x;
            acc.y += v.y;
        }
    }

    float dv = g_dinv[n];
    float2 b = ((const float2*)b2)[gl];
    float vx = dv * acc.x + b.x;
    float vy = dv * acc.y + b.y;

    // log-softmax over the 16 feats held by this 8-lane group
    float m = fmaxf(vx, vy);
    #pragma unroll
    for (int d = 4; d >= 1; d >>= 1)
        m = fmaxf(m, __shfl_xor_sync(gmask, m, d, 8));
    float s = expf(vx - m) + expf(vy - m);
    #pragma unroll
    for (int d = 4; d >= 1; d >>= 1)
        s += __shfl_xor_sync(gmask, s, d, 8);
    float ls = m + logf(s);

    ((float2*)out)[(long)n * 8 + gl] = make_float2(vx - ls, vy - ls);
}

// ---------------------------------------------------------------------------
extern "C" void kernel_launch(void* const* d_in, const int* in_sizes, int n_in,
                              void* d_out, int out_size) {
    const float* x  = (const float*)d_in[0];
    const int*   ei = (const int*)  d_in[1];
    const float* W1 = (const float*)d_in[2];
    const float* b1 = (const float*)d_in[3];
    const float* W2 = (const float*)d_in[4];
    const float* b2 = (const float*)d_in[5];
    const int* src = ei;
    const int* dst = ei + EE;

    cudaFuncSetAttribute(k_gemm1, cudaFuncAttributeMaxDynamicSharedMemorySize,
                         GEMM1_SMEM);

    // CSR build
    k_zero  <<<(NN + 255) / 256, 256>>>();
    k_count <<<(EE + 255) / 256, 256>>>(dst);
    k_scan1 <<<NB1, 1024>>>();
    k_scan2 <<<1, 128>>>();
    k_scan3 <<<NB1, 1024>>>();
    k_fill  <<<(EE + 255) / 256, 256>>>(src, dst);

    // Layer 1
    k_gemm1 <<<(NN + 255) / 256, 256, GEMM1_SMEM>>>(x, W1);
    k_agg1  <<<(NN * 32 + 255) / 256, 256>>>(b1);

    // Layer 2
    k_gemm2 <<<(NN + 255) / 256, 128>>>(W2);
    k_agg2  <<<(NN * 8 + 255) / 256, 256>>>(b2, (float*)d_out);
}

// round 6
// speedup vs baseline: 3.4625x; 1.1090x over previous
#include <cuda_runtime.h>
#include <cuda_fp16.h>

#define NN   100000
#define EE   1600000
#define DIN  128
#define DHID 64
#define DOUT 16
#define NB1  ((NN + 1023) / 1024)   // 98 scan blocks

// Scratch (__device__ globals; allocation-free rule).
__device__ float g_dinv[NN];
__device__ __align__(16) __half g_hs1h[NN * DHID];   // raw xW1, fp16
__device__ float g_x1[NN * DHID];
__device__ float g_hs2[NN * DOUT];
__device__ int   g_cnt[NN];
__device__ int   g_tmp[NB1 * 1024];
__device__ int   g_bsum[NB1];
__device__ int   g_offx[NN];
__device__ int   g_cur[NN];
__device__ int   g_esrc[EE];

__device__ __forceinline__ unsigned h2u(__half2 h) {
    return *reinterpret_cast<unsigned*>(&h);
}

// ---------------------------------------------------------------------------
__global__ void k_zero() {
    int i = blockIdx.x * blockDim.x + threadIdx.x;
    if (i < NN) g_cnt[i] = 0;
}

__global__ void k_count(const int* __restrict__ dst) {
    int e = blockIdx.x * blockDim.x + threadIdx.x;
    if (e < EE) atomicAdd(&g_cnt[dst[e]], 1);
}

__global__ __launch_bounds__(1024) void k_scan1() {
    __shared__ int ws[32];
    int i = blockIdx.x * 1024 + threadIdx.x;
    int lane = threadIdx.x & 31, wid = threadIdx.x >> 5;
    int v = (i < NN) ? g_cnt[i] : 0;
    int s = v;
    #pragma unroll
    for (int d = 1; d < 32; d <<= 1) {
        int t = __shfl_up_sync(0xffffffff, s, d);
        if (lane >= d) s += t;
    }
    if (lane == 31) ws[wid] = s;
    __syncthreads();
    if (wid == 0) {
        int w = ws[lane];
        #pragma unroll
        for (int d = 1; d < 32; d <<= 1) {
            int t = __shfl_up_sync(0xffffffff, w, d);
            if (lane >= d) w += t;
        }
        ws[lane] = w;
    }
    __syncthreads();
    int incl = s + (wid > 0 ? ws[wid - 1] : 0);
    g_tmp[i] = incl;
    if (threadIdx.x == 1023) g_bsum[blockIdx.x] = incl;
}

__global__ void k_scan2() {
    __shared__ int ws[4];
    int t = threadIdx.x;
    int lane = t & 31, wid = t >> 5;
    int v = (t < NB1) ? g_bsum[t] : 0;
    int s = v;
    #pragma unroll
    for (int d = 1; d < 32; d <<= 1) {
        int u = __shfl_up_sync(0xffffffff, s, d);
        if (lane >= d) s += u;
    }
    if (lane == 31) ws[wid] = s;
    __syncthreads();
    if (wid == 0 && lane < 4) {
        int w = ws[lane];
        #pragma unroll
        for (int d = 1; d < 4; d <<= 1) {
            int u = __shfl_up_sync(0xf, w, d);
            if (lane >= d) w += u;
        }
        ws[lane] = w;
    }
    __syncthreads();
    int incl = s + (wid > 0 ? ws[wid - 1] : 0);
    if (t < NB1) g_bsum[t] = incl;
}

__global__ __launch_bounds__(1024) void k_scan3() {
    int i = blockIdx.x * 1024 + threadIdx.x;
    if (i >= NN) return;
    int c = g_cnt[i];
    int excl = g_tmp[i] - c + (blockIdx.x > 0 ? g_bsum[blockIdx.x - 1] : 0);
    g_offx[i] = excl;
    g_cur[i]  = excl;
    g_dinv[i] = rsqrtf((float)(c + 1));
}

__global__ void k_fill(const int* __restrict__ src, const int* __restrict__ dst) {
    int e = blockIdx.x * blockDim.x + threadIdx.x;
    if (e >= EE) return;
    int d = dst[e];
    int p = atomicAdd(&g_cur[d], 1);
    g_esrc[p] = src[e];
}

// ---------------------------------------------------------------------------
// GEMM1: hs1h[row] = x[row] @ W1 (raw, fp16 out). 128 thr, 128 rows x 64 cols,
// 8x8/thr. Dyn smem: sW 32KB + xs[128][33] 16.9KB = 48.5KB -> 3 blocks/SM.
#define KC 32
#define GEMM1_SMEM ((DIN * DHID + 128 * (KC + 1)) * 4)
__global__ __launch_bounds__(128) void k_gemm1(const float* __restrict__ x,
                                               const float* __restrict__ W1) {
    extern __shared__ float smem[];
    float* sW = smem;
    float (*xs)[KC + 1] = (float (*)[KC + 1])(smem + DIN * DHID);

    int tid = threadIdx.x;
    int tx  = tid & 7;     // 8 col-groups x 8 cols
    int ty  = tid >> 3;    // 16 row-groups x 8 rows
    int rowBase = blockIdx.x * 128;

    {
        const float4* W4 = (const float4*)W1;
        float4* sW4 = (float4*)sW;
        #pragma unroll
        for (int i = 0; i < DIN * DHID / 4 / 128; i++)
            sW4[tid + i * 128] = W4[tid + i * 128];
    }

    float acc[8][8];
    #pragma unroll
    for (int r = 0; r < 8; r++)
        #pragma unroll
        for (int c = 0; c < 8; c++) acc[r][c] = 0.f;

    for (int kc = 0; kc < DIN; kc += KC) {
        __syncthreads();
        // stage x[rowBase..rowBase+127][kc..kc+31]: 1024 float4 / 128 thr
        #pragma unroll
        for (int it = 0; it < 8; it++) {
            int f   = tid + it * 128;
            int row = f >> 3;
            int k4  = (f & 7) * 4;
            float4 v = make_float4(0.f, 0.f, 0.f, 0.f);
            if (rowBase + row < NN)
                v = ((const float4*)x)[(long)(rowBase + row) * (DIN / 4) + ((kc + k4) >> 2)];
            xs[row][k4 + 0] = v.x;
            xs[row][k4 + 1] = v.y;
            xs[row][k4 + 2] = v.z;
            xs[row][k4 + 3] = v.w;
        }
        __syncthreads();

        #pragma unroll
        for (int k = 0; k < KC; k++) {
            float4 w0 = *(const float4*)&sW[(kc + k) * DHID + tx * 8];
            float4 w1 = *(const float4*)&sW[(kc + k) * DHID + tx * 8 + 4];
            #pragma unroll
            for (int r = 0; r < 8; r++) {
                float xv = xs[ty * 8 + r][k];
                acc[r][0] += xv * w0.x; acc[r][1] += xv * w0.y;
                acc[r][2] += xv * w0.z; acc[r][3] += xv * w0.w;
                acc[r][4] += xv * w1.x; acc[r][5] += xv * w1.y;
                acc[r][6] += xv * w1.z; acc[r][7] += xv * w1.w;
            }
        }
    }

    #pragma unroll
    for (int r = 0; r < 8; r++) {
        int row = rowBase + ty * 8 + r;
        if (row < NN) {
            uint4 u;
            u.x = h2u(__floats2half2_rn(acc[r][0], acc[r][1]));
            u.y = h2u(__floats2half2_rn(acc[r][2], acc[r][3]));
            u.z = h2u(__floats2half2_rn(acc[r][4], acc[r][5]));
            u.w = h2u(__floats2half2_rn(acc[r][6], acc[r][7]));
            *reinterpret_cast<uint4*>(g_hs1h + (long)row * DHID + tx * 8) = u;
        }
    }
}

// ---------------------------------------------------------------------------
// agg1: one warp per node; lane owns half2 (2 feats).
// x1[n] = relu(dinv[n]*(sum_s dinv[s]*hs[s] + dinv[n]*hs[n]) + b1)
__global__ __launch_bounds__(256) void k_agg1(const float* __restrict__ b1) {
    int warp = (blockIdx.x * 256 + threadIdx.x) >> 5;
    int lane = threadIdx.x & 31;
    if (warp >= NN) return;
    int n   = warp;
    int off = g_offx[n];
    int cnt = g_cnt[n];
    float dvn = g_dinv[n];

    const __half2* hs = (const __half2*)g_hs1h;
    float2 self = __half22float2(hs[(long)n * 32 + lane]);
    float2 acc;
    acc.x = self.x * dvn;
    acc.y = self.y * dvn;

    for (int base = 0; base < cnt; base += 32) {
        int idx = base + lane;
        int   e  = 0;
        float ds = 0.f;
        if (idx < cnt) {
            e  = g_esrc[off + idx];
            ds = g_dinv[e];
        }
        int m = min(32, cnt - base);
        for (int j = 0; j < m; j++) {
            int   s  = __shfl_sync(0xffffffff, e, j);
            float dj = __shfl_sync(0xffffffff, ds, j);
            float2 v = __half22float2(hs[(long)s * 32 + lane]);
            acc.x += v.x * dj;
            acc.y += v.y * dj;
        }
    }

    float2 b = ((const float2*)b1)[lane];
    float2 o;
    o.x = fmaxf(dvn * acc.x + b.x, 0.f);
    o.y = fmaxf(dvn * acc.y + b.y, 0.f);
    ((float2*)g_x1)[(long)n * 32 + lane] = o;
}

// ---------------------------------------------------------------------------
// GEMM2: hs2 = (x1 @ W2) * dinv. 128 thr -> 256x16 tile, 8x4/thr.
__global__ __launch_bounds__(128) void k_gemm2(const float* __restrict__ W2) {
    __shared__ float sW[DHID * DOUT];
    __shared__ float xs[256][KC + 1];

    int tid = threadIdx.x;
    int tx  = tid & 3;
    int ty  = tid >> 2;
    int rowBase = blockIdx.x * 256;

    {
        const float4* W4 = (const float4*)W2;
        float4* sW4 = (float4*)sW;
        #pragma unroll
        for (int i = 0; i < DHID * DOUT / 4 / 128; i++)
            sW4[tid + i * 128] = W4[tid + i * 128];
    }

    float acc[8][4];
    #pragma unroll
    for (int r = 0; r < 8; r++)
        #pragma unroll
        for (int c = 0; c < 4; c++) acc[r][c] = 0.f;

    for (int kc = 0; kc < DHID; kc += KC) {
        __syncthreads();
        #pragma unroll
        for (int it = 0; it < 16; it++) {
            int f   = tid + it * 128;
            int row = f >> 3;
            int k4  = (f & 7) * 4;
            float4 v = make_float4(0.f, 0.f, 0.f, 0.f);
            if (rowBase + row < NN)
                v = ((const float4*)g_x1)[(long)(rowBase + row) * (DHID / 4) + ((kc + k4) >> 2)];
            xs[row][k4 + 0] = v.x;
            xs[row][k4 + 1] = v.y;
            xs[row][k4 + 2] = v.z;
            xs[row][k4 + 3] = v.w;
        }
        __syncthreads();

        #pragma unroll
        for (int k = 0; k < KC; k++) {
            float4 w = *(const float4*)&sW[(kc + k) * DOUT + tx * 4];
            #pragma unroll
            for (int r = 0; r < 8; r++) {
                float xv = xs[ty * 8 + r][k];
                acc[r][0] += xv * w.x; acc[r][1] += xv * w.y;
                acc[r][2] += xv * w.z; acc[r][3] += xv * w.w;
            }
        }
    }

    #pragma unroll
    for (int r = 0; r < 8; r++) {
        int row = rowBase + ty * 8 + r;
        if (row < NN) {
            float dv = g_dinv[row];
            ((float4*)(g_hs2 + (long)row * DOUT))[tx] =
                make_float4(acc[r][0] * dv, acc[r][1] * dv, acc[r][2] * dv, acc[r][3] * dv);
        }
    }
}

// ---------------------------------------------------------------------------
// agg2: 8-lane group per node, per-group shuffle masks (groups diverge).
__global__ __launch_bounds__(256) void k_agg2(const float* __restrict__ b2,
                                              float* __restrict__ out) {
    int grp  = (blockIdx.x * 256 + threadIdx.x) >> 3;
    int gl   = threadIdx.x & 7;
    unsigned gmask = 0xFFu << (threadIdx.x & 24);
    if (grp >= NN) return;
    int n   = grp;
    int off = g_offx[n];
    int cnt = g_cnt[n];

    const float2* hs = (const float2*)g_hs2;
    float2 acc = hs[(long)n * 8 + gl];

    for (int base = 0; base < cnt; base += 8) {
        int idx = base + gl;
        int e   = (idx < cnt) ? g_esrc[off + idx] : 0;
        int m   = min(8, cnt - base);
        for (int j = 0; j < m; j++) {
            int s = __shfl_sync(gmask, e, j, 8);
            float2 v = hs[(long)s * 8 + gl];
            acc.x += v.x;
            acc.y += v.y;
        }
    }

    float dv = g_dinv[n];
    float2 b = ((const float2*)b2)[gl];
    float vx = dv * acc.x + b.x;
    float vy = dv * acc.y + b.y;

    float m = fmaxf(vx, vy);
    #pragma unroll
    for (int d = 4; d >= 1; d >>= 1)
        m = fmaxf(m, __shfl_xor_sync(gmask, m, d, 8));
    float s = expf(vx - m) + expf(vy - m);
    #pragma unroll
    for (int d = 4; d >= 1; d >>= 1)
        s += __shfl_xor_sync(gmask, s, d, 8);
    float ls = m + logf(s);

    ((float2*)out)[(long)n * 8 + gl] = make_float2(vx - ls, vy - ls);
}

// ---------------------------------------------------------------------------
extern "C" void kernel_launch(void* const* d_in, const int* in_sizes, int n_in,
                              void* d_out, int out_size) {
    const float* x  = (const float*)d_in[0];
    const int*   ei = (const int*)  d_in[1];
    const float* W1 = (const float*)d_in[2];
    const float* b1 = (const float*)d_in[3];
    const float* W2 = (const float*)d_in[4];
    const float* b2 = (const float*)d_in[5];
    const int* src = ei;
    const int* dst = ei + EE;

    // One-time host resources (no device memory involved). Work per call is
    // identical and deterministic; streams/events are reused across calls so
    // the captured graph sees a stable fork-join topology.
    static cudaStream_t s2 = nullptr;
    static cudaEvent_t  e0 = nullptr, e1 = nullptr;
    if (!s2) {
        cudaStreamCreate(&s2);
        cudaEventCreateWithFlags(&e0, cudaEventDisableTiming);
        cudaEventCreateWithFlags(&e1, cudaEventDisableTiming);
        cudaFuncSetAttribute(k_gemm1, cudaFuncAttributeMaxDynamicSharedMemorySize,
                             GEMM1_SMEM);
    }

    // Fork: CSR build on s2, concurrent with gemm1 on the main stream.
    cudaEventRecord(e0, 0);
    cudaStreamWaitEvent(s2, e0, 0);

    k_zero  <<<(NN + 255) / 256, 256, 0, s2>>>();
    k_count <<<(EE + 255) / 256, 256, 0, s2>>>(dst);
    k_scan1 <<<NB1, 1024, 0, s2>>>();
    k_scan2 <<<1, 128, 0, s2>>>();
    k_scan3 <<<NB1, 1024, 0, s2>>>();
    k_fill  <<<(EE + 255) / 256, 256, 0, s2>>>(src, dst);
    cudaEventRecord(e1, s2);

    k_gemm1 <<<(NN + 127) / 128, 128, GEMM1_SMEM>>>(x, W1);

    // Join: agg1 needs both gemm1 (main) and CSR (s2).
    cudaStreamWaitEvent(0, e1, 0);

    k_agg1  <<<(NN * 32 + 255) / 256, 256>>>(b1);
    k_gemm2 <<<(NN + 255) / 256, 128>>>(W2);
    k_agg2  <<<(NN * 8 + 255) / 256, 256>>>(b2, (float*)d_out);
}

// round 7
// speedup vs baseline: 3.8134x; 1.1014x over previous
#include <cuda_runtime.h>
#include <cuda_fp16.h>

#define NN   100000
#define EE   1600000
#define DIN  128
#define DHID 64
#define DOUT 16
#define NB1  ((NN + 1023) / 1024)   // 98 scan blocks

// Scratch (__device__ globals; allocation-free rule).
__device__ float g_dinv[NN];
__device__ __align__(16) __half g_hs1h[NN * DHID];   // raw xW1, fp16
__device__ float g_x1[NN * DHID];
__device__ float g_hs2[NN * DOUT];
__device__ int   g_cnt[NN];
__device__ int   g_tmp[NB1 * 1024];
__device__ int   g_bsum[NB1];
__device__ int   g_offx[NN];
__device__ int   g_cur[NN];
__device__ int   g_esrc[EE];

__device__ __forceinline__ unsigned h2u(__half2 h) {
    return *reinterpret_cast<unsigned*>(&h);
}

// ---------------------------------------------------------------------------
__global__ void k_zero() {
    int i = blockIdx.x * blockDim.x + threadIdx.x;
    if (i < NN) g_cnt[i] = 0;
}

__global__ void k_count(const int* __restrict__ dst) {
    int e = blockIdx.x * blockDim.x + threadIdx.x;
    if (e < EE) atomicAdd(&g_cnt[dst[e]], 1);
}

__global__ __launch_bounds__(1024) void k_scan1() {
    __shared__ int ws[32];
    int i = blockIdx.x * 1024 + threadIdx.x;
    int lane = threadIdx.x & 31, wid = threadIdx.x >> 5;
    int v = (i < NN) ? g_cnt[i] : 0;
    int s = v;
    #pragma unroll
    for (int d = 1; d < 32; d <<= 1) {
        int t = __shfl_up_sync(0xffffffff, s, d);
        if (lane >= d) s += t;
    }
    if (lane == 31) ws[wid] = s;
    __syncthreads();
    if (wid == 0) {
        int w = ws[lane];
        #pragma unroll
        for (int d = 1; d < 32; d <<= 1) {
            int t = __shfl_up_sync(0xffffffff, w, d);
            if (lane >= d) w += t;
        }
        ws[lane] = w;
    }
    __syncthreads();
    int incl = s + (wid > 0 ? ws[wid - 1] : 0);
    g_tmp[i] = incl;
    if (threadIdx.x == 1023) g_bsum[blockIdx.x] = incl;
}

__global__ void k_scan2() {
    __shared__ int ws[4];
    int t = threadIdx.x;
    int lane = t & 31, wid = t >> 5;
    int v = (t < NB1) ? g_bsum[t] : 0;
    int s = v;
    #pragma unroll
    for (int d = 1; d < 32; d <<= 1) {
        int u = __shfl_up_sync(0xffffffff, s, d);
        if (lane >= d) s += u;
    }
    if (lane == 31) ws[wid] = s;
    __syncthreads();
    if (wid == 0 && lane < 4) {
        int w = ws[lane];
        #pragma unroll
        for (int d = 1; d < 4; d <<= 1) {
            int u = __shfl_up_sync(0xf, w, d);
            if (lane >= d) w += u;
        }
        ws[lane] = w;
    }
    __syncthreads();
    int incl = s + (wid > 0 ? ws[wid - 1] : 0);
    if (t < NB1) g_bsum[t] = incl;
}

__global__ __launch_bounds__(1024) void k_scan3() {
    int i = blockIdx.x * 1024 + threadIdx.x;
    if (i >= NN) return;
    int c = g_cnt[i];
    int excl = g_tmp[i] - c + (blockIdx.x > 0 ? g_bsum[blockIdx.x - 1] : 0);
    g_offx[i] = excl;
    g_cur[i]  = excl;
    g_dinv[i] = rsqrtf((float)(c + 1));
}

__global__ void k_fill(const int* __restrict__ src, const int* __restrict__ dst) {
    int e = blockIdx.x * blockDim.x + threadIdx.x;
    if (e >= EE) return;
    int d = dst[e];
    int p = atomicAdd(&g_cur[d], 1);
    g_esrc[p] = src[e];
}

// ---------------------------------------------------------------------------
// GEMM1 on tensor cores (fp16 HMMA, fp32 accum): hs1h = x @ W1.
// Block 256 thr = 8 warps; block tile 256 rows x 64 cols; warp tile 32x64.
// smem: xs fp16 [256][136] (pad -> conflict-free ldmatrix), ws fp16 [128][72].
#define XS_STRIDE 136
#define WS_STRIDE 72
#define GEMM1_SMEM ((256 * XS_STRIDE + DIN * WS_STRIDE) * 2)

__device__ __forceinline__ void ldsm_x4(unsigned* d, unsigned addr) {
    asm volatile("ldmatrix.sync.aligned.m8n8.x4.shared.b16 {%0,%1,%2,%3}, [%4];"
        : "=r"(d[0]), "=r"(d[1]), "=r"(d[2]), "=r"(d[3]) : "r"(addr));
}
__device__ __forceinline__ void ldsm_x4_t(unsigned* d, unsigned addr) {
    asm volatile("ldmatrix.sync.aligned.m8n8.x4.trans.shared.b16 {%0,%1,%2,%3}, [%4];"
        : "=r"(d[0]), "=r"(d[1]), "=r"(d[2]), "=r"(d[3]) : "r"(addr));
}
__device__ __forceinline__ void mma16816(float* c, const unsigned* a,
                                         unsigned b0, unsigned b1) {
    asm volatile("mma.sync.aligned.m16n8k16.row.col.f32.f16.f16.f32 "
        "{%0,%1,%2,%3}, {%4,%5,%6,%7}, {%8,%9}, {%0,%1,%2,%3};"
        : "+f"(c[0]), "+f"(c[1]), "+f"(c[2]), "+f"(c[3])
        : "r"(a[0]), "r"(a[1]), "r"(a[2]), "r"(a[3]), "r"(b0), "r"(b1));
}

__global__ __launch_bounds__(256) void k_gemm1(const float* __restrict__ x,
                                               const float* __restrict__ W1) {
    extern __shared__ __half sm[];
    __half* xs = sm;                        // [256][XS_STRIDE]
    __half* ws = sm + 256 * XS_STRIDE;      // [128][WS_STRIDE]
    int tid = threadIdx.x;
    int rowBase = blockIdx.x * 256;

    // stage W1 -> fp16 smem
    for (int i = tid; i < DIN * DHID; i += 256) {
        int k = i >> 6, n = i & 63;
        ws[k * WS_STRIDE + n] = __float2half(W1[i]);
    }
    // stage x rows -> fp16 smem (guarded; stale smem in OOB rows unused)
    const float4* x4 = (const float4*)x;
    #pragma unroll
    for (int it = 0; it < 32; it++) {
        int f   = tid + it * 256;
        int row = f >> 5, c4 = f & 31;
        if (rowBase + row < NN) {
            float4 v = x4[(long)(rowBase + row) * 32 + c4];
            uint2 u;
            u.x = h2u(__floats2half2_rn(v.x, v.y));
            u.y = h2u(__floats2half2_rn(v.z, v.w));
            *reinterpret_cast<uint2*>(&xs[row * XS_STRIDE + c4 * 4]) = u;
        }
    }
    __syncthreads();

    int warp = tid >> 5, lane = tid & 31;
    int g = lane >> 3, r = lane & 7;        // ldmatrix quadrant / row-in-tile

    float c[2][8][4];
    #pragma unroll
    for (int mt = 0; mt < 2; mt++)
        #pragma unroll
        for (int nt = 0; nt < 8; nt++)
            #pragma unroll
            for (int q = 0; q < 4; q++) c[mt][nt][q] = 0.f;

    unsigned xs_base = (unsigned)__cvta_generic_to_shared(xs);
    unsigned ws_base = (unsigned)__cvta_generic_to_shared(ws);

    #pragma unroll
    for (int kk = 0; kk < 8; kk++) {        // K = 8 x 16
        unsigned a[2][4];
        #pragma unroll
        for (int mt = 0; mt < 2; mt++) {
            int m = warp * 32 + mt * 16 + (g & 1) * 8 + r;
            unsigned addr = xs_base + (m * XS_STRIDE + kk * 16 + (g >> 1) * 8) * 2;
            ldsm_x4(a[mt], addr);
        }
        #pragma unroll
        for (int np = 0; np < 4; np++) {    // pairs of n-tiles
            // quadrants: g0=(klo,n0) g1=(khi,n0) g2=(klo,n1) g3=(khi,n1)
            int k = kk * 16 + (g & 1) * 8 + r;
            int n = np * 16 + (g >> 1) * 8;
            unsigned addr = ws_base + (k * WS_STRIDE + n) * 2;
            unsigned b[4];
            ldsm_x4_t(b, addr);
            mma16816(c[0][np * 2 + 0], a[0], b[0], b[1]);
            mma16816(c[0][np * 2 + 1], a[0], b[2], b[3]);
            mma16816(c[1][np * 2 + 0], a[1], b[0], b[1]);
            mma16816(c[1][np * 2 + 1], a[1], b[2], b[3]);
        }
    }

    // epilogue: C frags -> half2 stores
    int rq = lane >> 2, cq = (lane & 3) * 2;
    #pragma unroll
    for (int mt = 0; mt < 2; mt++) {
        int row0 = rowBase + warp * 32 + mt * 16 + rq;
        #pragma unroll
        for (int nt = 0; nt < 8; nt++) {
            int col = nt * 8 + cq;
            if (row0 < NN)
                *reinterpret_cast<__half2*>(g_hs1h + (long)row0 * DHID + col) =
                    __floats2half2_rn(c[mt][nt][0], c[mt][nt][1]);
            if (row0 + 8 < NN)
                *reinterpret_cast<__half2*>(g_hs1h + (long)(row0 + 8) * DHID + col) =
                    __floats2half2_rn(c[mt][nt][2], c[mt][nt][3]);
        }
    }
}

// ---------------------------------------------------------------------------
// agg1: one warp per node; lane owns half2 (2 feats).
__global__ __launch_bounds__(256) void k_agg1(const float* __restrict__ b1) {
    int warp = (blockIdx.x * 256 + threadIdx.x) >> 5;
    int lane = threadIdx.x & 31;
    if (warp >= NN) return;
    int n   = warp;
    int off = g_offx[n];
    int cnt = g_cnt[n];
    float dvn = g_dinv[n];

    const __half2* hs = (const __half2*)g_hs1h;
    float2 self = __half22float2(hs[(long)n * 32 + lane]);
    float2 acc;
    acc.x = self.x * dvn;
    acc.y = self.y * dvn;

    for (int base = 0; base < cnt; base += 32) {
        int idx = base + lane;
        int   e  = 0;
        float ds = 0.f;
        if (idx < cnt) {
            e  = g_esrc[off + idx];
            ds = g_dinv[e];
        }
        int m = min(32, cnt - base);
        for (int j = 0; j < m; j++) {
            int   s  = __shfl_sync(0xffffffff, e, j);
            float dj = __shfl_sync(0xffffffff, ds, j);
            float2 v = __half22float2(hs[(long)s * 32 + lane]);
            acc.x += v.x * dj;
            acc.y += v.y * dj;
        }
    }

    float2 b = ((const float2*)b1)[lane];
    float2 o;
    o.x = fmaxf(dvn * acc.x + b.x, 0.f);
    o.y = fmaxf(dvn * acc.y + b.y, 0.f);
    ((float2*)g_x1)[(long)n * 32 + lane] = o;
}

// ---------------------------------------------------------------------------
// GEMM2: hs2 = (x1 @ W2) * dinv. 128 thr -> 256x16 tile, 8x4/thr.
#define KC 32
__global__ __launch_bounds__(128) void k_gemm2(const float* __restrict__ W2) {
    __shared__ float sW[DHID * DOUT];
    __shared__ float xs[256][KC + 1];

    int tid = threadIdx.x;
    int tx  = tid & 3;
    int ty  = tid >> 2;
    int rowBase = blockIdx.x * 256;

    {
        const float4* W4 = (const float4*)W2;
        float4* sW4 = (float4*)sW;
        #pragma unroll
        for (int i = 0; i < DHID * DOUT / 4 / 128; i++)
            sW4[tid + i * 128] = W4[tid + i * 128];
    }

    float acc[8][4];
    #pragma unroll
    for (int r = 0; r < 8; r++)
        #pragma unroll
        for (int c = 0; c < 4; c++) acc[r][c] = 0.f;

    for (int kc = 0; kc < DHID; kc += KC) {
        __syncthreads();
        #pragma unroll
        for (int it = 0; it < 16; it++) {
            int f   = tid + it * 128;
            int row = f >> 3;
            int k4  = (f & 7) * 4;
            float4 v = make_float4(0.f, 0.f, 0.f, 0.f);
            if (rowBase + row < NN)
                v = ((const float4*)g_x1)[(long)(rowBase + row) * (DHID / 4) + ((kc + k4) >> 2)];
            xs[row][k4 + 0] = v.x;
            xs[row][k4 + 1] = v.y;
            xs[row][k4 + 2] = v.z;
            xs[row][k4 + 3] = v.w;
        }
        __syncthreads();

        #pragma unroll
        for (int k = 0; k < KC; k++) {
            float4 w = *(const float4*)&sW[(kc + k) * DOUT + tx * 4];
            #pragma unroll
            for (int r = 0; r < 8; r++) {
                float xv = xs[ty * 8 + r][k];
                acc[r][0] += xv * w.x; acc[r][1] += xv * w.y;
                acc[r][2] += xv * w.z; acc[r][3] += xv * w.w;
            }
        }
    }

    #pragma unroll
    for (int r = 0; r < 8; r++) {
        int row = rowBase + ty * 8 + r;
        if (row < NN) {
            float dv = g_dinv[row];
            ((float4*)(g_hs2 + (long)row * DOUT))[tx] =
                make_float4(acc[r][0] * dv, acc[r][1] * dv, acc[r][2] * dv, acc[r][3] * dv);
        }
    }
}

// ---------------------------------------------------------------------------
// agg2: 8-lane group per node, per-group shuffle masks (groups diverge).
__global__ __launch_bounds__(256) void k_agg2(const float* __restrict__ b2,
                                              float* __restrict__ out) {
    int grp  = (blockIdx.x * 256 + threadIdx.x) >> 3;
    int gl   = threadIdx.x & 7;
    unsigned gmask = 0xFFu << (threadIdx.x & 24);
    if (grp >= NN) return;
    int n   = grp;
    int off = g_offx[n];
    int cnt = g_cnt[n];

    const float2* hs = (const float2*)g_hs2;
    float2 acc = hs[(long)n * 8 + gl];

    for (int base = 0; base < cnt; base += 8) {
        int idx = base + gl;
        int e   = (idx < cnt) ? g_esrc[off + idx] : 0;
        int m   = min(8, cnt - base);
        for (int j = 0; j < m; j++) {
            int s = __shfl_sync(gmask, e, j, 8);
            float2 v = hs[(long)s * 8 + gl];
            acc.x += v.x;
            acc.y += v.y;
        }
    }

    float dv = g_dinv[n];
    float2 b = ((const float2*)b2)[gl];
    float vx = dv * acc.x + b.x;
    float vy = dv * acc.y + b.y;

    float m = fmaxf(vx, vy);
    #pragma unroll
    for (int d = 4; d >= 1; d >>= 1)
        m = fmaxf(m, __shfl_xor_sync(gmask, m, d, 8));
    float s = expf(vx - m) + expf(vy - m);
    #pragma unroll
    for (int d = 4; d >= 1; d >>= 1)
        s += __shfl_xor_sync(gmask, s, d, 8);
    float ls = m + logf(s);

    ((float2*)out)[(long)n * 8 + gl] = make_float2(vx - ls, vy - ls);
}

// ---------------------------------------------------------------------------
extern "C" void kernel_launch(void* const* d_in, const int* in_sizes, int n_in,
                              void* d_out, int out_size) {
    const float* x  = (const float*)d_in[0];
    const int*   ei = (const int*)  d_in[1];
    const float* W1 = (const float*)d_in[2];
    const float* b1 = (const float*)d_in[3];
    const float* W2 = (const float*)d_in[4];
    const float* b2 = (const float*)d_in[5];
    const int* src = ei;
    const int* dst = ei + EE;

    static cudaStream_t s2 = nullptr;
    static cudaEvent_t  e0 = nullptr, e1 = nullptr;
    if (!s2) {
        cudaStreamCreate(&s2);
        cudaEventCreateWithFlags(&e0, cudaEventDisableTiming);
        cudaEventCreateWithFlags(&e1, cudaEventDisableTiming);
        cudaFuncSetAttribute(k_gemm1, cudaFuncAttributeMaxDynamicSharedMemorySize,
                             GEMM1_SMEM);
    }

    // Fork: CSR build on s2, concurrent with gemm1 on the main stream.
    cudaEventRecord(e0, 0);
    cudaStreamWaitEvent(s2, e0, 0);

    k_zero  <<<(NN + 255) / 256, 256, 0, s2>>>();
    k_count <<<(EE + 255) / 256, 256, 0, s2>>>(dst);
    k_scan1 <<<NB1, 1024, 0, s2>>>();
    k_scan2 <<<1, 128, 0, s2>>>();
    k_scan3 <<<NB1, 1024, 0, s2>>>();
    k_fill  <<<(EE + 255) / 256, 256, 0, s2>>>(src, dst);
    cudaEventRecord(e1, s2);

    k_gemm1 <<<(NN + 255) / 256, 256, GEMM1_SMEM>>>(x, W1);

    // Join: agg1 needs both gemm1 (main) and CSR (s2).
    cudaStreamWaitEvent(0, e1, 0);

    k_agg1  <<<(NN * 32 + 255) / 256, 256>>>(b1);
    k_gemm2 <<<(NN + 255) / 256, 128>>>(W2);
    k_agg2  <<<(NN * 8 + 255) / 256, 256>>>(b2, (float*)d_out);
}